// round 12
// baseline (speedup 1.0000x reference)
#include <cuda_runtime.h>
#include <math_constants.h>
#include <cstdint>

// FilterDetection: score threshold + morphological opening (erode k=4 -> dilate k=4)
// cv2 semantics: erode offsets [-2,+1] (border +inf), dilate offsets [-1,+2]
// (eroded plane outside image = -inf).
//
// Register-pipeline kernel, R3 geometry: WARP = 128-col x 64-row strip,
// 8 warps/CTA, 512 CTAs. This round: explicit distance-1 software prefetch of
// each row (main + halo LDG issued one full step before consumption) so the
// DRAM long-scoreboard is fully overlapped with compute; halo compressed to
// 3 shared scalars with all selects done at load time.

#define CHUNK  128   // columns per warp (32 lanes x float4)
#define RSTRIP 64    // output rows per warp
#define WARPS  8     // warps per CTA
#define N_SCORE 32000

__global__ __launch_bounds__(32 * WARPS, 4)
void open_kernel(const float* __restrict__ mask, float* __restrict__ out,
                 const float* __restrict__ score, float* __restrict__ out_score) {
    const int lane  = threadIdx.x;
    const int warp  = threadIdx.y;
    const int chunk = blockIdx.x;                       // 0..7
    const int c0    = chunk * CHUNK;
    const int r0    = (blockIdx.y * WARPS + warp) * RSTRIP;
    const int col   = c0 + lane * 4;
    const float* img  = mask + (size_t)blockIdx.z * (1024u * 1024u);
    float*       oimg = out  + (size_t)blockIdx.z * (1024u * 1024u);

    // ---- fused score threshold (independent work) ----
    {
        int gtid = (((blockIdx.z * gridDim.y + blockIdx.y) * gridDim.x + blockIdx.x)
                    * (32 * WARPS)) + warp * 32 + lane;
        if (gtid < N_SCORE) {
            float s = score[gtid];
            out_score[gtid] = (s >= 0.5f) ? s : 0.0f;
        }
    }

    const bool leftEdge  = (chunk == 0);
    const bool rightEdge = (chunk == 7);
    const float INF = CUDART_INF_F;

    // Halo: lane 0 fetches cols c0-4..c0-1, lane 31 fetches c0+128..c0+131,
    // interior lanes harmlessly refetch their own word (same sectors).
    const bool pL = (lane == 0)  && !leftEdge;
    const bool pR = (lane == 31) && !rightEdge;
    const bool pOK = pL || pR;
    int haloCol = col;
    if (pL) haloCol = c0 - 4;
    if (pR) haloCol = c0 + CHUNK;

    // pipeline state
    float4 hprev;  float hlprev, hr0prev, hr1prev;
    float4 pring[2]; float plr[2], pr0r[2], pr1r[2];
    float4 gprev;
    float4 sring[2];

    // Load row for step t. chk=false when ir is statically in-bounds.
    // Produces bound-selected v and compressed halo scalars:
    //   lane 0 : (m0,m1,m2) = in[ir][c0-3..c0-1]
    //   lane 31: (m0,m1,m2) = in[ir][c0+128..c0+130]
    auto loadRow = [&](int t, bool chk, float4& v, float& m0, float& m1, float& m2)
        __attribute__((always_inline)) {
        const int ir = r0 - 3 + t;
        const bool rok = chk ? ((unsigned)ir < 1024u) : true;
        const int irc = chk ? min(max(ir, 0), 1023) : ir;
        const float* rowp = img + (size_t)irc * 1024;
        float4 vr = *reinterpret_cast<const float4*>(rowp + col);
        float4 hb = *reinterpret_cast<const float4*>(rowp + haloCol);
        if (chk) {
            v.x = rok ? vr.x : INF; v.y = rok ? vr.y : INF;
            v.z = rok ? vr.z : INF; v.w = rok ? vr.w : INF;
        } else {
            v = vr;
        }
        const bool ok = chk ? (pOK && rok) : pOK;
        m0 = ok ? (pL ? hb.y : hb.x) : INF;
        m1 = ok ? (pL ? hb.z : hb.y) : INF;
        m2 = ok ? (pL ? hb.w : hb.z) : INF;
    };

    auto stepC = [&](int t, float4 v, float m0, float m1, float m2,
                     bool doP, bool doEV, bool doS, bool doOut, bool interior)
        __attribute__((always_inline)) {
        const int ir  = r0 - 3 + t;
        const int par = t & 1;

        // ---- horizontal erode: h_j = min(v_{j-2..j+1}) (van Herk) ----
        float vrx = __shfl_down_sync(0xffffffffu, v.x, 1);
        float vwu = __shfl_up_sync  (0xffffffffu, v.w, 1);
        if (lane == 31) vrx = m0;                 // xrx
        if (lane == 0)  vwu = m2;                 // xlw
        float4 q;
        q.x = fminf(v.x, v.y); q.y = fminf(v.y, v.z);
        q.z = fminf(v.z, v.w); q.w = fminf(v.w, vrx);
        float mm01 = fminf(m0, m1);
        float mm12 = fminf(m1, m2);
        float qpz = __shfl_up_sync(0xffffffffu, q.z, 1);
        if (lane == 0) qpz = mm12;                // min(xlz,xlw)
        float qpw = fminf(vwu, v.x);              // q.w of lane-1
        float4 h;
        h.x = fminf(qpz, q.x); h.y = fminf(qpw, q.y);
        h.z = fminf(q.x, q.z); h.w = fminf(q.y, q.w);
        float hl  = fminf(mm01, qpw);             // h @ col c0-1   (lane 0)
        float hr0 = fminf(q.z, mm01);             // h @ col c0+128 (lane 31)
        float hr1 = fminf(q.w, mm12);             // h @ col c0+129 (lane 31)

        if (doP) {
            // vertical erode pairwise
            float4 pn;
            pn.x = fminf(h.x, hprev.x); pn.y = fminf(h.y, hprev.y);
            pn.z = fminf(h.z, hprev.z); pn.w = fminf(h.w, hprev.w);
            float pln  = fminf(hl,  hlprev);
            float pr0n = fminf(hr0, hr0prev);
            float pr1n = fminf(hr1, hr1prev);

            if (doEV) {
                const int e = ir - 1;
                const bool eok = interior || ((unsigned)e < 1024u);
                float4 po = pring[par];
                float4 ev;
                if (interior) {
                    ev.x = fminf(po.x, pn.x); ev.y = fminf(po.y, pn.y);
                    ev.z = fminf(po.z, pn.z); ev.w = fminf(po.w, pn.w);
                } else {
                    ev.x = eok ? fminf(po.x, pn.x) : -INF;
                    ev.y = eok ? fminf(po.y, pn.y) : -INF;
                    ev.z = eok ? fminf(po.z, pn.z) : -INF;
                    ev.w = eok ? fminf(po.w, pn.w) : -INF;
                }
                float evL  = (eok && !leftEdge)  ? fminf(plr[par],  pln)  : -INF;
                float evR0 = (eok && !rightEdge) ? fminf(pr0r[par], pr0n) : -INF;
                float evR1 = (eok && !rightEdge) ? fminf(pr1r[par], pr1n) : -INF;

                // horizontal dilate: g_j = max(ev_{j-1..j+2})
                float evwu = __shfl_up_sync  (0xffffffffu, ev.w, 1);
                float evxd = __shfl_down_sync(0xffffffffu, ev.x, 1);
                float evyd = __shfl_down_sync(0xffffffffu, ev.y, 1);
                if (lane == 0)  evwu = evL;
                if (lane == 31) { evxd = evR0; evyd = evR1; }
                float4 r;
                r.x = fmaxf(evwu, ev.x); r.y = fmaxf(ev.x, ev.y);
                r.z = fmaxf(ev.y, ev.z); r.w = fmaxf(ev.z, ev.w);
                float rnx = fmaxf(ev.w, evxd);
                float rny = fmaxf(evxd, evyd);
                float4 g;
                g.x = fmaxf(r.x, r.z); g.y = fmaxf(r.y, r.w);
                g.z = fmaxf(r.z, rnx); g.w = fmaxf(r.w, rny);

                if (doS) {
                    // vertical dilate pairwise
                    float4 sn;
                    sn.x = fmaxf(g.x, gprev.x); sn.y = fmaxf(g.y, gprev.y);
                    sn.z = fmaxf(g.z, gprev.z); sn.w = fmaxf(g.w, gprev.w);
                    if (doOut) {
                        float4 so = sring[par];
                        float4 o4;
                        o4.x = fmaxf(so.x, sn.x); o4.y = fmaxf(so.y, sn.y);
                        o4.z = fmaxf(so.z, sn.z); o4.w = fmaxf(so.w, sn.w);
                        // threshold (monotone => commutes with opening)
                        o4.x = (o4.x >= 0.5f) ? o4.x : 0.0f;
                        o4.y = (o4.y >= 0.5f) ? o4.y : 0.0f;
                        o4.z = (o4.z >= 0.5f) ? o4.z : 0.0f;
                        o4.w = (o4.w >= 0.5f) ? o4.w : 0.0f;
                        const int o = ir - 3;
                        *reinterpret_cast<float4*>(oimg + (size_t)o * 1024 + col) = o4;
                    }
                    sring[par] = sn;
                }
                gprev = g;
            }
            pring[par] = pn; plr[par] = pln;
            pr0r[par] = pr0n; pr1r[par] = pr1n;
        }
        hprev = h; hlprev = hl; hr0prev = hr0; hr1prev = hr1;
    };

    // ---- distance-1 prefetch pipeline ----
    float4 vn; float n0, n1, n2;
    loadRow(0, true, vn, n0, n1, n2);

    // prologue (peeled, checked)
    {
        float4 v = vn; float a0 = n0, a1 = n1, a2 = n2;
        loadRow(1, true, vn, n0, n1, n2);
        stepC(0, v, a0, a1, a2, false, false, false, false, false);
    }
    {
        float4 v = vn; float a0 = n0, a1 = n1, a2 = n2;
        loadRow(2, true, vn, n0, n1, n2);
        stepC(1, v, a0, a1, a2, true, false, false, false, false);
    }
    {
        float4 v = vn; float a0 = n0, a1 = n1, a2 = n2;
        loadRow(3, true, vn, n0, n1, n2);
        stepC(2, v, a0, a1, a2, true, false, false, false, false);
    }
    {
        float4 v = vn; float a0 = n0, a1 = n1, a2 = n2;
        loadRow(4, true, vn, n0, n1, n2);
        stepC(3, v, a0, a1, a2, true, true, false, false, false);
    }
    {
        float4 v = vn; float a0 = n0, a1 = n1, a2 = n2;
        loadRow(5, true, vn, n0, n1, n2);
        stepC(4, v, a0, a1, a2, true, true, true, false, false);
    }
    {
        float4 v = vn; float a0 = n0, a1 = n1, a2 = n2;
        loadRow(6, false, vn, n0, n1, n2);   // t=6 -> ir=r0+3, in-bounds
        stepC(5, v, a0, a1, a2, true, true, true, false, false);
    }

    // interior steady state: t in [6,65]; prefetched rows t+1 in [7,66] are
    // statically in-bounds (ir = r0-2+t <= r0+63 <= 1023).
#pragma unroll 4
    for (int t = 6; t < 66; ++t) {
        float4 v = vn; float a0 = n0, a1 = n1, a2 = n2;
        loadRow(t + 1, false, vn, n0, n1, n2);
        stepC(t, v, a0, a1, a2, true, true, true, true, true);
    }
    // checked tail (bottom strips run past row 1023)
#pragma unroll
    for (int t = 66; t < RSTRIP + 6; ++t) {
        float4 v = vn; float a0 = n0, a1 = n1, a2 = n2;
        if (t < RSTRIP + 5) loadRow(t + 1, true, vn, n0, n1, n2);
        stepC(t, v, a0, a1, a2, true, true, true, true, false);
    }
}

extern "C" void kernel_launch(void* const* d_in, const int* in_sizes, int n_in,
                              void* d_out, int out_size) {
    const float* score = (const float*)d_in[0];   // 32*1000
    const float* mask  = (const float*)d_in[1];   // 32*1024*1024
    float* out = (float*)d_out;

    float* out_score = out;
    float* out_mask  = out + N_SCORE;

    dim3 grid(1024 / CHUNK, 1024 / (RSTRIP * WARPS), 32);   // (8, 2, 32) = 512 CTAs
    dim3 block(32, WARPS);
    open_kernel<<<grid, block>>>(mask, out_mask, score, out_score);
}